// round 4
// baseline (speedup 1.0000x reference)
#include <cuda_runtime.h>
#include <cstdint>
#include <cstddef>

// Problem dims
static constexpr int Bc = 32;
static constexpr int Tc = 2048;
static constexpr int Dc = 256;
static constexpr int Hc = 512;
static constexpr int Oc = 256;
static constexpr int BT = Bc * Tc;          // 65536

// Scratch (static device arrays — allocation-free per harness rules)
__device__ float g_xw[(size_t)BT * Hc];     // 128 MB: x@W_ih^T + bias
__device__ float g_z [(size_t)BT * Hc];     // 128 MB: fallback z storage

// ---------------------------------------------------------------------------
// Packed f32x2 helpers (sm_100+ dual-FP32 pipe)
// ---------------------------------------------------------------------------
__device__ __forceinline__ void fma2(unsigned long long& d,
                                     unsigned long long a,
                                     unsigned long long b) {
    asm("fma.rn.f32x2 %0, %1, %2, %0;" : "+l"(d) : "l"(a), "l"(b));
}
__device__ __forceinline__ float unpack_sum(unsigned long long a) {
    float lo, hi;
    asm("mov.b64 {%0, %1}, %2;" : "=f"(lo), "=f"(hi) : "l"(a));
    return lo + hi;
}

// ---------------------------------------------------------------------------
// Kernel 1/3: C[M,N] = A[M,K] @ B[N,K]^T + bias1[N] (+ bias2[N])
// Classic 128x128x16 fp32 tile, 256 threads, 8x8 microtile, double-buffered.
// ---------------------------------------------------------------------------
__global__ void __launch_bounds__(256, 2)
gemm_tn_kernel(const float* __restrict__ A, const float* __restrict__ Bm,
               const float* __restrict__ bias1, const float* __restrict__ bias2,
               float* __restrict__ C, int M, int N, int K)
{
    __shared__ float As[2][16][128];
    __shared__ float Bs[2][16][128];

    const int tid = threadIdx.x;
    const int bm = blockIdx.x * 128;
    const int bn = blockIdx.y * 128;
    const int lr = tid >> 2;            // 0..63  (row within tile, +64 on 2nd pass)
    const int lk = (tid & 3) << 2;      // 0,4,8,12 (k offset, float4)
    const int tm = (tid >> 4) << 3;     // 0..120 step 8
    const int tn = (tid & 15) << 3;     // 0..120 step 8

    float acc[8][8];
#pragma unroll
    for (int i = 0; i < 8; i++)
#pragma unroll
        for (int j = 0; j < 8; j++) acc[i][j] = 0.f;

    auto load_tile = [&](int buf, int kt) {
#pragma unroll
        for (int p = 0; p < 2; p++) {
            const float4 av = *reinterpret_cast<const float4*>(
                A + (size_t)(bm + lr + p * 64) * K + kt + lk);
            As[buf][lk + 0][lr + p * 64] = av.x;
            As[buf][lk + 1][lr + p * 64] = av.y;
            As[buf][lk + 2][lr + p * 64] = av.z;
            As[buf][lk + 3][lr + p * 64] = av.w;
            const float4 bv = *reinterpret_cast<const float4*>(
                Bm + (size_t)(bn + lr + p * 64) * K + kt + lk);
            Bs[buf][lk + 0][lr + p * 64] = bv.x;
            Bs[buf][lk + 1][lr + p * 64] = bv.y;
            Bs[buf][lk + 2][lr + p * 64] = bv.z;
            Bs[buf][lk + 3][lr + p * 64] = bv.w;
        }
    };

    load_tile(0, 0);
    __syncthreads();

    const int nk = K >> 4;
    for (int kt = 0; kt < nk; kt++) {
        const int cur = kt & 1;
        if (kt + 1 < nk) load_tile(cur ^ 1, (kt + 1) << 4);
#pragma unroll
        for (int kk = 0; kk < 16; kk++) {
            float a[8], b[8];
            *reinterpret_cast<float4*>(&a[0]) =
                *reinterpret_cast<const float4*>(&As[cur][kk][tm]);
            *reinterpret_cast<float4*>(&a[4]) =
                *reinterpret_cast<const float4*>(&As[cur][kk][tm + 4]);
            *reinterpret_cast<float4*>(&b[0]) =
                *reinterpret_cast<const float4*>(&Bs[cur][kk][tn]);
            *reinterpret_cast<float4*>(&b[4]) =
                *reinterpret_cast<const float4*>(&Bs[cur][kk][tn + 4]);
#pragma unroll
            for (int i = 0; i < 8; i++)
#pragma unroll
                for (int j = 0; j < 8; j++) acc[i][j] += a[i] * b[j];
        }
        __syncthreads();
    }

    // Epilogue: bias + store (float4)
    float bv[8];
#pragma unroll
    for (int j = 0; j < 8; j++) {
        float b = bias1 ? bias1[bn + tn + j] : 0.f;
        if (bias2) b += bias2[bn + tn + j];
        bv[j] = b;
    }
#pragma unroll
    for (int i = 0; i < 8; i++) {
        float* cp = C + (size_t)(bm + tm + i) * N + bn + tn;
        float4 v0, v1;
        v0.x = acc[i][0] + bv[0]; v0.y = acc[i][1] + bv[1];
        v0.z = acc[i][2] + bv[2]; v0.w = acc[i][3] + bv[3];
        v1.x = acc[i][4] + bv[4]; v1.y = acc[i][5] + bv[5];
        v1.z = acc[i][6] + bv[6]; v1.w = acc[i][7] + bv[7];
        *reinterpret_cast<float4*>(cp)     = v0;
        *reinterpret_cast<float4*>(cp + 4) = v1;
    }
}

// ---------------------------------------------------------------------------
// Kernel 2/3: the sequential recurrence.
// 16 clusters x 8 CTAs; cluster c owns batches {2c, 2c+1}.
// CTA rank r owns output slice j in [64r, 64r+64); its 512x64 W_hh slice lives
// in registers (packed f32x2 along k). h is replicated in every CTA's smem
// (double-buffered); the 128 writer threads broadcast h_new to all 8 ranks via
// DSMEM stores, then one cluster barrier per step.
// ---------------------------------------------------------------------------
__global__ void __cluster_dims__(8, 1, 1) __launch_bounds__(512, 1)
rnn_scan_kernel(const float* __restrict__ xw, const float* __restrict__ h0,
                const float* __restrict__ W_hh, float* __restrict__ z)
{
    __shared__ __align__(16) float hbuf[2][2][Hc];  // [phase][batch][k]
    __shared__ float red[2][8][64];                 // [batch][kchunk][j]

    const int tid = threadIdx.x;
    uint32_t rank;
    asm("mov.u32 %0, %%cluster_ctarank;" : "=r"(rank));
    const int cid = blockIdx.x >> 3;
    const int b0  = cid * 2;

    const int jloc  = tid & 63;
    const int kc    = tid >> 6;          // 0..7
    const int jg    = (int)rank * 64 + jloc;
    const int kbase = kc * 64;

    // W_hh[jg][kbase .. kbase+63] into 32 packed f32x2 registers
    unsigned long long w[32];
    {
        const float4* wp =
            reinterpret_cast<const float4*>(W_hh + (size_t)jg * Hc + kbase);
#pragma unroll
        for (int i = 0; i < 16; i++) {
            float4 v = wp[i];
            unsigned long long p0, p1;
            asm("mov.b64 %0, {%1, %2};" : "=l"(p0) : "f"(v.x), "f"(v.y));
            asm("mov.b64 %0, {%1, %2};" : "=l"(p1) : "f"(v.z), "f"(v.w));
            w[2 * i]     = p0;
            w[2 * i + 1] = p1;
        }
    }

    // initial h (phase 0) — each CTA holds the full h for both batches
    for (int idx = tid; idx < 2 * Hc; idx += 512) {
        const int bb = idx >> 9;     // Hc == 512
        const int k  = idx & 511;
        hbuf[0][bb][k] = h0[(size_t)(b0 + bb) * Hc + k];
    }
    __syncthreads();
    asm volatile("barrier.cluster.arrive.aligned;" ::: "memory");
    asm volatile("barrier.cluster.wait.aligned;" ::: "memory");

    // writer identity (threads 0..127 finalize one (batch, j) each)
    const bool is_writer = (tid < 128);
    const int  wb  = tid >> 6;           // 0/1 (valid when is_writer)
    const int  wj  = tid & 63;
    const int  wjg = (int)rank * 64 + wj;
    const size_t bstride = (size_t)Tc * Hc;

    uint32_t haddr[2];
    haddr[0] = (uint32_t)__cvta_generic_to_shared(&hbuf[0][wb][wjg]);
    haddr[1] = (uint32_t)__cvta_generic_to_shared(&hbuf[1][wb][wjg]);

    for (int t = 0; t < Tc; t++) {
        const int p = t & 1;

        float xwv = 0.f;
        if (is_writer)   // prefetch: latency hidden under the FMA phase
            xwv = __ldg(xw + (size_t)(b0 + wb) * bstride + (size_t)t * Hc + wjg);

        unsigned long long acc0 = 0ull, acc1 = 0ull;  // packed {0,0}
        const ulonglong2* h0p =
            reinterpret_cast<const ulonglong2*>(&hbuf[p][0][kbase]);
        const ulonglong2* h1p =
            reinterpret_cast<const ulonglong2*>(&hbuf[p][1][kbase]);
#pragma unroll
        for (int i = 0; i < 16; i++) {
            const ulonglong2 ha = h0p[i];
            const ulonglong2 hb = h1p[i];
            fma2(acc0, w[2 * i],     ha.x);
            fma2(acc1, w[2 * i],     hb.x);
            fma2(acc0, w[2 * i + 1], ha.y);
            fma2(acc1, w[2 * i + 1], hb.y);
        }
        red[0][kc][jloc] = unpack_sum(acc0);
        red[1][kc][jloc] = unpack_sum(acc1);
        __syncthreads();

        if (is_writer) {
            float s = xwv;
#pragma unroll
            for (int q = 0; q < 8; q++) s += red[wb][q][wj];
            z[(size_t)(b0 + wb) * bstride + (size_t)t * Hc + wjg] = s;
            const uint32_t la = haddr[p ^ 1];
#pragma unroll
            for (uint32_t rr = 0; rr < 8; rr++) {
                uint32_t ra;
                asm("mapa.shared::cluster.u32 %0, %1, %2;"
                    : "=r"(ra) : "r"(la), "r"(rr));
                asm volatile("st.shared::cluster.f32 [%0], %1;"
                             :: "r"(ra), "f"(s));
            }
        }
        asm volatile("barrier.cluster.arrive.aligned;" ::: "memory");
        asm volatile("barrier.cluster.wait.aligned;" ::: "memory");
    }
}

// ---------------------------------------------------------------------------
// Kernel 3/3: in-place row softmax over O=256 (one warp per row)
// ---------------------------------------------------------------------------
__global__ void __launch_bounds__(256)
softmax256_kernel(float* __restrict__ P, int rows)
{
    const int row  = blockIdx.x * 8 + (threadIdx.x >> 5);
    const int lane = threadIdx.x & 31;
    if (row >= rows) return;
    float4* p = reinterpret_cast<float4*>(P + (size_t)row * Oc);
    float4 v0 = p[lane];
    float4 v1 = p[lane + 32];

    float m = fmaxf(fmaxf(fmaxf(v0.x, v0.y), fmaxf(v0.z, v0.w)),
                    fmaxf(fmaxf(v1.x, v1.y), fmaxf(v1.z, v1.w)));
#pragma unroll
    for (int o = 16; o > 0; o >>= 1)
        m = fmaxf(m, __shfl_xor_sync(0xffffffffu, m, o));

    v0.x = expf(v0.x - m); v0.y = expf(v0.y - m);
    v0.z = expf(v0.z - m); v0.w = expf(v0.w - m);
    v1.x = expf(v1.x - m); v1.y = expf(v1.y - m);
    v1.z = expf(v1.z - m); v1.w = expf(v1.w - m);

    float s = v0.x + v0.y + v0.z + v0.w + v1.x + v1.y + v1.z + v1.w;
#pragma unroll
    for (int o = 16; o > 0; o >>= 1)
        s += __shfl_xor_sync(0xffffffffu, s, o);

    const float inv = 1.0f / s;
    v0.x *= inv; v0.y *= inv; v0.z *= inv; v0.w *= inv;
    v1.x *= inv; v1.y *= inv; v1.z *= inv; v1.w *= inv;
    p[lane]      = v0;
    p[lane + 32] = v1;
}

// ---------------------------------------------------------------------------
// Launch: xw GEMM -> sequential scan -> logits GEMM -> softmax
// ---------------------------------------------------------------------------
extern "C" void kernel_launch(void* const* d_in, const int* in_sizes, int n_in,
                              void* d_out, int out_size)
{
    (void)in_sizes; (void)n_in;
    const float* x     = (const float*)d_in[0];
    const float* h0    = (const float*)d_in[1];
    const float* W_ih  = (const float*)d_in[2];
    const float* W_hh  = (const float*)d_in[3];
    const float* b_ih  = (const float*)d_in[4];
    const float* b_hh  = (const float*)d_in[5];
    const float* W_lin = (const float*)d_in[6];
    const float* b_lin = (const float*)d_in[7];
    float* outp = (float*)d_out;

    float* xw = nullptr;
    cudaGetSymbolAddress((void**)&xw, g_xw);

    // Outputs are (out, z) concatenated when out_size covers both; otherwise
    // z lives in scratch and only softmax(out) is returned.
    float* zbuf = nullptr;
    if ((long long)out_size >= (long long)BT * (Oc + Hc))
        zbuf = outp + (size_t)BT * Oc;
    else
        cudaGetSymbolAddress((void**)&zbuf, g_z);

    // 1) xw = x @ W_ih^T + (b_ih + b_hh)   [BT, H]
    gemm_tn_kernel<<<dim3(BT / 128, Hc / 128), 256>>>(
        x, W_ih, b_ih, b_hh, xw, BT, Hc, Dc);

    // 2) sequential scan -> z [B, T, H]
    rnn_scan_kernel<<<128, 512>>>(xw, h0, W_hh, zbuf);

    // 3) logits = z @ W_lin^T + b_lin  [BT, O]
    gemm_tn_kernel<<<dim3(BT / 128, Oc / 128), 256>>>(
        zbuf, W_lin, b_lin, nullptr, outp, BT, Oc, Hc);

    // 4) softmax rows in place
    softmax256_kernel<<<BT / 8, 256>>>(outp, BT);
}